// round 3
// baseline (speedup 1.0000x reference)
#include <cuda_runtime.h>
#include <math.h>

#define S    64
#define NF   196608
#define HD   128
#define K2   (2*NF)
#define NSUB (NF/32)   // 6144 k-subtiles of 32

// Scratch (device globals — no allocation allowed)
__device__ float g_U[S*HD];     // U[t*HD+h] = (W_z @ z_t)[h]
__device__ float g_Mt[HD*HD];   // Mt[c*HD+h] = (W_p @ fc2_w)[h][c]  (transposed for conflict-free scan reads)
__device__ float g_v[HD];       // W_p @ fc2_b
__device__ float g_w0[HD];      // W_p @ prev_gen0
__device__ float g_H2[S*HD];    // h2 state per step

__device__ __forceinline__ float sigm(float x) { return 1.f / (1.f + expf(-x)); }

// ---------------- zero the atomic accumulators ----------------
__global__ void k_zero() {
    int n = S*HD + HD*HD + 2*HD;
    for (int i = blockIdx.x*blockDim.x + threadIdx.x; i < n; i += gridDim.x*blockDim.x) {
        if (i < S*HD)               g_U[i] = 0.f;
        else if (i < S*HD + HD*HD)  g_Mt[i - S*HD] = 0.f;
        else if (i < S*HD + HD*HD + HD) g_v[i - S*HD - HD*HD] = 0.f;
        else                        g_w0[i - S*HD - HD*HD - HD] = 0.f;
    }
}

// ---------------- GEMM 1: U[128 x 64] = W_z[128,K] * Z^T[K,64] (split-K, NT) ----------------
__global__ void __launch_bounds__(256, 2) k_gemm_u(const float* __restrict__ fc1w,
                                                   const float* __restrict__ z) {
    __shared__ float As[128*33];
    __shared__ float Zs[64*33];
    int tid = threadIdx.x;
    int ty = tid >> 4, tx = tid & 15;
    float acc[8][4];
    #pragma unroll
    for (int r = 0; r < 8; r++)
        #pragma unroll
        for (int c = 0; c < 4; c++) acc[r][c] = 0.f;

    for (int st = blockIdx.x; st < NSUB; st += gridDim.x) {
        int kb = st << 5;
        for (int idx = tid; idx < 128*32; idx += 256) {
            int row = idx >> 5, kk = idx & 31;
            As[row*33 + kk] = fc1w[row*K2 + kb + kk];
        }
        for (int idx = tid; idx < 64*32; idx += 256) {
            int t = idx >> 5, kk = idx & 31;
            Zs[t*33 + kk] = z[t*NF + kb + kk];
        }
        __syncthreads();
        #pragma unroll
        for (int kk = 0; kk < 32; kk++) {
            float a[8], b[4];
            #pragma unroll
            for (int r = 0; r < 8; r++) a[r] = As[(ty + 16*r)*33 + kk];
            #pragma unroll
            for (int c = 0; c < 4; c++) b[c] = Zs[(tx + 16*c)*33 + kk];
            #pragma unroll
            for (int r = 0; r < 8; r++)
                #pragma unroll
                for (int c = 0; c < 4; c++) acc[r][c] += a[r]*b[c];
        }
        __syncthreads();
    }
    #pragma unroll
    for (int r = 0; r < 8; r++)
        #pragma unroll
        for (int c = 0; c < 4; c++)
            atomicAdd(&g_U[(tx + 16*c)*HD + (ty + 16*r)], acc[r][c]);
}

// ------- GEMM 2: M[128 x 128] = W_p[128,K] * fc2_w[K,128] (+ W_p@fc2_b, W_p@pg0) -------
__global__ void __launch_bounds__(256, 2) k_gemm_m(const float* __restrict__ fc1w,
                                                   const float* __restrict__ fc2w,
                                                   const float* __restrict__ fc2b,
                                                   const float* __restrict__ pg0) {
    __shared__ float As[128*33];
    __shared__ float Bs[32*128];
    __shared__ float Es[64];
    int tid = threadIdx.x;
    int ty = tid >> 4, tx = tid & 15;
    int erow = tid & 127, ewhich = tid >> 7;   // which: 0 -> fc2_b dot, 1 -> pg0 dot
    float acc[8][8];
    float accE = 0.f;
    #pragma unroll
    for (int r = 0; r < 8; r++)
        #pragma unroll
        for (int c = 0; c < 8; c++) acc[r][c] = 0.f;

    for (int st = blockIdx.x; st < NSUB; st += gridDim.x) {
        int kb = st << 5;
        for (int idx = tid; idx < 128*32; idx += 256) {
            int row = idx >> 5, kk = idx & 31;
            As[row*33 + kk] = fc1w[row*K2 + NF + kb + kk];
        }
        for (int idx = tid; idx < 32*128; idx += 256) {
            int kk = idx >> 7, c = idx & 127;
            Bs[kk*128 + c] = fc2w[(kb + kk)*128 + c];
        }
        if (tid < 64) Es[tid] = (tid < 32) ? fc2b[kb + tid] : pg0[kb + (tid - 32)];
        __syncthreads();
        #pragma unroll
        for (int kk = 0; kk < 32; kk++) {
            float a[8], b[8];
            #pragma unroll
            for (int r = 0; r < 8; r++) a[r] = As[(ty + 16*r)*33 + kk];
            #pragma unroll
            for (int c = 0; c < 8; c++) b[c] = Bs[kk*128 + tx + 16*c];
            #pragma unroll
            for (int r = 0; r < 8; r++)
                #pragma unroll
                for (int c = 0; c < 8; c++) acc[r][c] += a[r]*b[c];
            accE += As[erow*33 + kk] * Es[ewhich*32 + kk];
        }
        __syncthreads();
    }
    #pragma unroll
    for (int r = 0; r < 8; r++)
        #pragma unroll
        for (int c = 0; c < 8; c++)
            atomicAdd(&g_Mt[(tx + 16*c)*HD + (ty + 16*r)], acc[r][c]);
    atomicAdd(ewhich ? &g_w0[erow] : &g_v[erow], accE);
}

// ---------------- Phase 2: the 64-step recurrent scan (tiny, 1 block) ----------------
__global__ void __launch_bounds__(256) k_scan(
    const float* __restrict__ h1_in, const float* __restrict__ c1_in,
    const float* __restrict__ h2_in, const float* __restrict__ c2_in,
    const float* __restrict__ fc1b,
    const float* __restrict__ wih1, const float* __restrict__ whh1,
    const float* __restrict__ bih1, const float* __restrict__ bhh1,
    const float* __restrict__ wih2, const float* __restrict__ whh2,
    const float* __restrict__ bih2, const float* __restrict__ bhh2,
    float* __restrict__ out, int out_size)
{
    __shared__ __align__(16) float Us[S*HD];
    __shared__ __align__(16) float xs[HD], h1s[HD], c1s[HD], h2s[HD], c2s[HD];
    __shared__ __align__(16) float gs[4*HD];
    __shared__ float b1s[4*HD], b2s[4*HD], xbv[HD], xbw0[HD];
    int tid = threadIdx.x;

    for (int i = tid; i < S*HD; i += 256) Us[i] = g_U[i];
    for (int i = tid; i < 4*HD; i += 256) { b1s[i] = bih1[i] + bhh1[i]; b2s[i] = bih2[i] + bhh2[i]; }
    if (tid < HD) {
        h1s[tid] = h1_in[tid]; c1s[tid] = c1_in[tid];
        h2s[tid] = h2_in[tid]; c2s[tid] = c2_in[tid];
        xbv[tid]  = fc1b[tid] + g_v[tid];
        xbw0[tid] = fc1b[tid] + g_w0[tid];
    }
    __syncthreads();

    for (int t = 0; t < S; t++) {
        // x_t = relu(U_t + W_p@prev_gen + fc1_b)
        if (tid < HD) {
            float a;
            if (t == 0) {
                a = Us[tid] + xbw0[tid];
            } else {
                a = Us[t*HD + tid] + xbv[tid];
                #pragma unroll 8
                for (int c = 0; c < HD; c++) a += g_Mt[c*HD + tid] * h2s[c];
            }
            xs[tid] = fmaxf(a, 0.f);
        }
        __syncthreads();

        // LSTM1 gates: 512 rows, 2 per thread
        {
            const float4* xv = (const float4*)xs;
            const float4* hv = (const float4*)h1s;
            #pragma unroll
            for (int rr = 0; rr < 2; rr++) {
                int r = tid + rr*256;
                const float4* wi = (const float4*)(wih1 + r*HD);
                const float4* wh = (const float4*)(whh1 + r*HD);
                float a = b1s[r];
                #pragma unroll 8
                for (int j = 0; j < 32; j++) {
                    float4 w = wi[j], x4 = xv[j];
                    a += w.x*x4.x + w.y*x4.y + w.z*x4.z + w.w*x4.w;
                    float4 u = wh[j], h4 = hv[j];
                    a += u.x*h4.x + u.y*h4.y + u.z*h4.z + u.w*h4.w;
                }
                gs[r] = a;
            }
        }
        __syncthreads();
        if (tid < HD) {
            float gi = gs[tid], gf = gs[HD+tid], gg = gs[2*HD+tid], go = gs[3*HD+tid];
            float c = sigm(gf)*c1s[tid] + sigm(gi)*tanhf(gg);
            c1s[tid] = c;
            h1s[tid] = sigm(go)*tanhf(c);
        }
        __syncthreads();

        // LSTM2 gates (input = h1)
        {
            const float4* xv = (const float4*)h1s;
            const float4* hv = (const float4*)h2s;
            #pragma unroll
            for (int rr = 0; rr < 2; rr++) {
                int r = tid + rr*256;
                const float4* wi = (const float4*)(wih2 + r*HD);
                const float4* wh = (const float4*)(whh2 + r*HD);
                float a = b2s[r];
                #pragma unroll 8
                for (int j = 0; j < 32; j++) {
                    float4 w = wi[j], x4 = xv[j];
                    a += w.x*x4.x + w.y*x4.y + w.z*x4.z + w.w*x4.w;
                    float4 u = wh[j], h4 = hv[j];
                    a += u.x*h4.x + u.y*h4.y + u.z*h4.z + u.w*h4.w;
                }
                gs[r] = a;
            }
        }
        __syncthreads();
        if (tid < HD) {
            float gi = gs[tid], gf = gs[HD+tid], gg = gs[2*HD+tid], go = gs[3*HD+tid];
            float c = sigm(gf)*c2s[tid] + sigm(gi)*tanhf(gg);
            c2s[tid] = c;
            float h = sigm(go)*tanhf(c);
            h2s[tid] = h;
            g_H2[t*HD + tid] = h;
        }
        __syncthreads();
    }

    if (out_size >= S*NF + 4*HD && tid < HD) {
        out[S*NF + 0*HD + tid] = h1s[tid];
        out[S*NF + 1*HD + tid] = c1s[tid];
        out[S*NF + 2*HD + tid] = h2s[tid];
        out[S*NF + 3*HD + tid] = c2s[tid];
    }
}

// ------- GEMM 3: out[t,k] = fc2_w[k,:] . h2_t + fc2_b[k] + y[t,k] (NT, K=128) -------
__global__ void __launch_bounds__(256) k_out(const float* __restrict__ fc2w,
                                             const float* __restrict__ fc2b,
                                             const float* __restrict__ y,
                                             float* __restrict__ out) {
    __shared__ __align__(16) float H2s[S*HD];
    int tid = threadIdx.x;
    for (int i = tid; i < S*HD; i += 256) H2s[i] = g_H2[i];
    __syncthreads();

    int k = blockIdx.x*256 + tid;
    const float4* w4 = (const float4*)(fc2w + k*HD);
    const float4* h4 = (const float4*)H2s;
    float acc[S];
    #pragma unroll
    for (int t = 0; t < S; t++) acc[t] = 0.f;

    #pragma unroll 4
    for (int j = 0; j < 32; j++) {
        float4 w = w4[j];
        #pragma unroll
        for (int t = 0; t < S; t++) {
            float4 h = h4[t*32 + j];
            acc[t] += w.x*h.x + w.y*h.y + w.z*h.z + w.w*h.w;
        }
    }
    float b = fc2b[k];
    #pragma unroll 4
    for (int t = 0; t < S; t++)
        out[t*NF + k] = acc[t] + b + y[t*NF + k];
}

// ---------------- launcher ----------------
extern "C" void kernel_launch(void* const* d_in, const int* in_sizes, int n_in,
                              void* d_out, int out_size) {
    const float* z    = (const float*)d_in[0];
    const float* y    = (const float*)d_in[1];
    const float* pg0  = (const float*)d_in[2];
    const float* h1   = (const float*)d_in[3];
    const float* c1   = (const float*)d_in[4];
    const float* h2   = (const float*)d_in[5];
    const float* c2   = (const float*)d_in[6];
    const float* fc1w = (const float*)d_in[7];
    const float* fc1b = (const float*)d_in[8];
    const float* wih1 = (const float*)d_in[9];
    const float* whh1 = (const float*)d_in[10];
    const float* bih1 = (const float*)d_in[11];
    const float* bhh1 = (const float*)d_in[12];
    const float* wih2 = (const float*)d_in[13];
    const float* whh2 = (const float*)d_in[14];
    const float* bih2 = (const float*)d_in[15];
    const float* bhh2 = (const float*)d_in[16];
    const float* fc2w = (const float*)d_in[17];
    const float* fc2b = (const float*)d_in[18];
    float* out = (float*)d_out;

    k_zero<<<32, 256>>>();
    k_gemm_u<<<296, 256>>>(fc1w, z);
    k_gemm_m<<<296, 256>>>(fc1w, fc2w, fc2b, pg0);
    k_scan<<<1, 256>>>(h1, c1, h2, c2, fc1b,
                       wih1, whh1, bih1, bhh1,
                       wih2, whh2, bih2, bhh2,
                       out, out_size);
    k_out<<<768, 256>>>(fc2w, fc2b, y, out);
}

// round 4
// speedup vs baseline: 1.0031x; 1.0031x over previous
#include <cuda_runtime.h>
#include <math.h>

#define S    64
#define NF   196608
#define HD   128
#define K2   (2*NF)
#define NSUB (NF/32)   // 6144 k-subtiles of 32

// Scratch (device globals — no allocation allowed)
__device__ float g_U[S*HD];     // U[t*HD+h] = (W_z @ z_t)[h]
__device__ float g_Mt[HD*HD];   // Mt[c*HD+h] = (W_p @ fc2_w)[h][c]  (transposed for conflict-free scan reads)
__device__ float g_v[HD];       // W_p @ fc2_b
__device__ float g_w0[HD];      // W_p @ prev_gen0
__device__ float g_H2[S*HD];    // h2 state per step

__device__ __forceinline__ float sigm(float x) { return 1.f / (1.f + expf(-x)); }

// ---------------- zero the atomic accumulators ----------------
__global__ void k_zero() {
    int n = S*HD + HD*HD + 2*HD;
    for (int i = blockIdx.x*blockDim.x + threadIdx.x; i < n; i += gridDim.x*blockDim.x) {
        if (i < S*HD)               g_U[i] = 0.f;
        else if (i < S*HD + HD*HD)  g_Mt[i - S*HD] = 0.f;
        else if (i < S*HD + HD*HD + HD) g_v[i - S*HD - HD*HD] = 0.f;
        else                        g_w0[i - S*HD - HD*HD - HD] = 0.f;
    }
}

// ---------------- GEMM 1: U[128 x 64] = W_z[128,K] * Z^T[K,64] (split-K, NT) ----------------
__global__ void __launch_bounds__(256, 2) k_gemm_u(const float* __restrict__ fc1w,
                                                   const float* __restrict__ z) {
    __shared__ float As[128*33];
    __shared__ float Zs[64*33];
    int tid = threadIdx.x;
    int ty = tid >> 4, tx = tid & 15;
    float acc[8][4];
    #pragma unroll
    for (int r = 0; r < 8; r++)
        #pragma unroll
        for (int c = 0; c < 4; c++) acc[r][c] = 0.f;

    for (int st = blockIdx.x; st < NSUB; st += gridDim.x) {
        int kb = st << 5;
        for (int idx = tid; idx < 128*32; idx += 256) {
            int row = idx >> 5, kk = idx & 31;
            As[row*33 + kk] = fc1w[row*K2 + kb + kk];
        }
        for (int idx = tid; idx < 64*32; idx += 256) {
            int t = idx >> 5, kk = idx & 31;
            Zs[t*33 + kk] = z[t*NF + kb + kk];
        }
        __syncthreads();
        #pragma unroll
        for (int kk = 0; kk < 32; kk++) {
            float a[8], b[4];
            #pragma unroll
            for (int r = 0; r < 8; r++) a[r] = As[(ty + 16*r)*33 + kk];
            #pragma unroll
            for (int c = 0; c < 4; c++) b[c] = Zs[(tx + 16*c)*33 + kk];
            #pragma unroll
            for (int r = 0; r < 8; r++)
                #pragma unroll
                for (int c = 0; c < 4; c++) acc[r][c] += a[r]*b[c];
        }
        __syncthreads();
    }
    #pragma unroll
    for (int r = 0; r < 8; r++)
        #pragma unroll
        for (int c = 0; c < 4; c++)
            atomicAdd(&g_U[(tx + 16*c)*HD + (ty + 16*r)], acc[r][c]);
}

// ------- GEMM 2: M[128 x 128] = W_p[128,K] * fc2_w[K,128] (+ W_p@fc2_b, W_p@pg0) -------
__global__ void __launch_bounds__(256, 2) k_gemm_m(const float* __restrict__ fc1w,
                                                   const float* __restrict__ fc2w,
                                                   const float* __restrict__ fc2b,
                                                   const float* __restrict__ pg0) {
    __shared__ float As[128*33];
    __shared__ float Bs[32*128];
    __shared__ float Es[64];
    int tid = threadIdx.x;
    int ty = tid >> 4, tx = tid & 15;
    int erow = tid & 127, ewhich = tid >> 7;   // which: 0 -> fc2_b dot, 1 -> pg0 dot
    float acc[8][8];
    float accE = 0.f;
    #pragma unroll
    for (int r = 0; r < 8; r++)
        #pragma unroll
        for (int c = 0; c < 8; c++) acc[r][c] = 0.f;

    for (int st = blockIdx.x; st < NSUB; st += gridDim.x) {
        int kb = st << 5;
        for (int idx = tid; idx < 128*32; idx += 256) {
            int row = idx >> 5, kk = idx & 31;
            As[row*33 + kk] = fc1w[row*K2 + NF + kb + kk];
        }
        for (int idx = tid; idx < 32*128; idx += 256) {
            int kk = idx >> 7, c = idx & 127;
            Bs[kk*128 + c] = fc2w[(kb + kk)*128 + c];
        }
        if (tid < 64) Es[tid] = (tid < 32) ? fc2b[kb + tid] : pg0[kb + (tid - 32)];
        __syncthreads();
        #pragma unroll
        for (int kk = 0; kk < 32; kk++) {
            float a[8], b[8];
            #pragma unroll
            for (int r = 0; r < 8; r++) a[r] = As[(ty + 16*r)*33 + kk];
            #pragma unroll
            for (int c = 0; c < 8; c++) b[c] = Bs[kk*128 + tx + 16*c];
            #pragma unroll
            for (int r = 0; r < 8; r++)
                #pragma unroll
                for (int c = 0; c < 8; c++) acc[r][c] += a[r]*b[c];
            accE += As[erow*33 + kk] * Es[ewhich*32 + kk];
        }
        __syncthreads();
    }
    #pragma unroll
    for (int r = 0; r < 8; r++)
        #pragma unroll
        for (int c = 0; c < 8; c++)
            atomicAdd(&g_Mt[(tx + 16*c)*HD + (ty + 16*r)], acc[r][c]);
    atomicAdd(ewhich ? &g_w0[erow] : &g_v[erow], accE);
}

// ---------------- Phase 2: the 64-step recurrent scan (tiny, 1 block) ----------------
__global__ void __launch_bounds__(256) k_scan(
    const float* __restrict__ h1_in, const float* __restrict__ c1_in,
    const float* __restrict__ h2_in, const float* __restrict__ c2_in,
    const float* __restrict__ fc1b,
    const float* __restrict__ wih1, const float* __restrict__ whh1,
    const float* __restrict__ bih1, const float* __restrict__ bhh1,
    const float* __restrict__ wih2, const float* __restrict__ whh2,
    const float* __restrict__ bih2, const float* __restrict__ bhh2,
    float* __restrict__ out, int out_size)
{
    __shared__ __align__(16) float Us[S*HD];
    __shared__ __align__(16) float xs[HD], h1s[HD], c1s[HD], h2s[HD], c2s[HD];
    __shared__ __align__(16) float gs[4*HD];
    __shared__ float b1s[4*HD], b2s[4*HD], xbv[HD], xbw0[HD];
    int tid = threadIdx.x;

    for (int i = tid; i < S*HD; i += 256) Us[i] = g_U[i];
    for (int i = tid; i < 4*HD; i += 256) { b1s[i] = bih1[i] + bhh1[i]; b2s[i] = bih2[i] + bhh2[i]; }
    if (tid < HD) {
        h1s[tid] = h1_in[tid]; c1s[tid] = c1_in[tid];
        h2s[tid] = h2_in[tid]; c2s[tid] = c2_in[tid];
        xbv[tid]  = fc1b[tid] + g_v[tid];
        xbw0[tid] = fc1b[tid] + g_w0[tid];
    }
    __syncthreads();

    for (int t = 0; t < S; t++) {
        // x_t = relu(U_t + W_p@prev_gen + fc1_b)
        if (tid < HD) {
            float a;
            if (t == 0) {
                a = Us[tid] + xbw0[tid];
            } else {
                a = Us[t*HD + tid] + xbv[tid];
                #pragma unroll 8
                for (int c = 0; c < HD; c++) a += g_Mt[c*HD + tid] * h2s[c];
            }
            xs[tid] = fmaxf(a, 0.f);
        }
        __syncthreads();

        // LSTM1 gates: 512 rows, 2 per thread
        {
            const float4* xv = (const float4*)xs;
            const float4* hv = (const float4*)h1s;
            #pragma unroll
            for (int rr = 0; rr < 2; rr++) {
                int r = tid + rr*256;
                const float4* wi = (const float4*)(wih1 + r*HD);
                const float4* wh = (const float4*)(whh1 + r*HD);
                float a = b1s[r];
                #pragma unroll 8
                for (int j = 0; j < 32; j++) {
                    float4 w = wi[j], x4 = xv[j];
                    a += w.x*x4.x + w.y*x4.y + w.z*x4.z + w.w*x4.w;
                    float4 u = wh[j], h4 = hv[j];
                    a += u.x*h4.x + u.y*h4.y + u.z*h4.z + u.w*h4.w;
                }
                gs[r] = a;
            }
        }
        __syncthreads();
        if (tid < HD) {
            float gi = gs[tid], gf = gs[HD+tid], gg = gs[2*HD+tid], go = gs[3*HD+tid];
            float c = sigm(gf)*c1s[tid] + sigm(gi)*tanhf(gg);
            c1s[tid] = c;
            h1s[tid] = sigm(go)*tanhf(c);
        }
        __syncthreads();

        // LSTM2 gates (input = h1)
        {
            const float4* xv = (const float4*)h1s;
            const float4* hv = (const float4*)h2s;
            #pragma unroll
            for (int rr = 0; rr < 2; rr++) {
                int r = tid + rr*256;
                const float4* wi = (const float4*)(wih2 + r*HD);
                const float4* wh = (const float4*)(whh2 + r*HD);
                float a = b2s[r];
                #pragma unroll 8
                for (int j = 0; j < 32; j++) {
                    float4 w = wi[j], x4 = xv[j];
                    a += w.x*x4.x + w.y*x4.y + w.z*x4.z + w.w*x4.w;
                    float4 u = wh[j], h4 = hv[j];
                    a += u.x*h4.x + u.y*h4.y + u.z*h4.z + u.w*h4.w;
                }
                gs[r] = a;
            }
        }
        __syncthreads();
        if (tid < HD) {
            float gi = gs[tid], gf = gs[HD+tid], gg = gs[2*HD+tid], go = gs[3*HD+tid];
            float c = sigm(gf)*c2s[tid] + sigm(gi)*tanhf(gg);
            c2s[tid] = c;
            float h = sigm(go)*tanhf(c);
            h2s[tid] = h;
            g_H2[t*HD + tid] = h;
        }
        __syncthreads();
    }

    if (out_size >= S*NF + 4*HD && tid < HD) {
        out[S*NF + 0*HD + tid] = h1s[tid];
        out[S*NF + 1*HD + tid] = c1s[tid];
        out[S*NF + 2*HD + tid] = h2s[tid];
        out[S*NF + 3*HD + tid] = c2s[tid];
    }
}

// ------- GEMM 3: out[t,k] = fc2_w[k,:] . h2_t + fc2_b[k] + y[t,k] (NT, K=128) -------
__global__ void __launch_bounds__(256) k_out(const float* __restrict__ fc2w,
                                             const float* __restrict__ fc2b,
                                             const float* __restrict__ y,
                                             float* __restrict__ out) {
    __shared__ __align__(16) float H2s[S*HD];
    int tid = threadIdx.x;
    for (int i = tid; i < S*HD; i += 256) H2s[i] = g_H2[i];
    __syncthreads();

    int k = blockIdx.x*256 + tid;
    const float4* w4 = (const float4*)(fc2w + k*HD);
    const float4* h4 = (const float4*)H2s;
    float acc[S];
    #pragma unroll
    for (int t = 0; t < S; t++) acc[t] = 0.f;

    #pragma unroll 4
    for (int j = 0; j < 32; j++) {
        float4 w = w4[j];
        #pragma unroll
        for (int t = 0; t < S; t++) {
            float4 h = h4[t*32 + j];
            acc[t] += w.x*h.x + w.y*h.y + w.z*h.z + w.w*h.w;
        }
    }
    float b = fc2b[k];
    #pragma unroll 4
    for (int t = 0; t < S; t++)
        out[t*NF + k] = acc[t] + b + y[t*NF + k];
}

// ---------------- launcher ----------------
extern "C" void kernel_launch(void* const* d_in, const int* in_sizes, int n_in,
                              void* d_out, int out_size) {
    const float* z    = (const float*)d_in[0];
    const float* y    = (const float*)d_in[1];
    const float* pg0  = (const float*)d_in[2];
    const float* h1   = (const float*)d_in[3];
    const float* c1   = (const float*)d_in[4];
    const float* h2   = (const float*)d_in[5];
    const float* c2   = (const float*)d_in[6];
    const float* fc1w = (const float*)d_in[7];
    const float* fc1b = (const float*)d_in[8];
    const float* wih1 = (const float*)d_in[9];
    const float* whh1 = (const float*)d_in[10];
    const float* bih1 = (const float*)d_in[11];
    const float* bhh1 = (const float*)d_in[12];
    const float* wih2 = (const float*)d_in[13];
    const float* whh2 = (const float*)d_in[14];
    const float* bih2 = (const float*)d_in[15];
    const float* bhh2 = (const float*)d_in[16];
    const float* fc2w = (const float*)d_in[17];
    const float* fc2b = (const float*)d_in[18];
    float* out = (float*)d_out;

    k_zero<<<32, 256>>>();
    k_gemm_u<<<296, 256>>>(fc1w, z);
    k_gemm_m<<<296, 256>>>(fc1w, fc2w, fc2b, pg0);
    k_scan<<<1, 256>>>(h1, c1, h2, c2, fc1b,
                       wih1, whh1, bih1, bhh1,
                       wih2, whh2, bih2, bhh2,
                       out, out_size);
    k_out<<<768, 256>>>(fc2w, fc2b, y, out);
}

// round 5
// speedup vs baseline: 1.8813x; 1.8755x over previous
#include <cuda_runtime.h>
#include <math.h>

#define S    64
#define NF   196608
#define HD   128
#define K2   (2*NF)
#define NSUB (NF/32)   // 6144 k-subtiles of 32

// Scratch (device globals — no allocation allowed)
__device__ float g_U[S*HD];     // U[t*HD+h] = (W_z @ z_t)[h]
__device__ float g_M[HD*HD];    // g_M[h*HD+c] = (W_p @ fc2_w)[h][c]  (row-major for coalesced warp-per-row)
__device__ float g_v[HD];       // W_p @ fc2_b
__device__ float g_w0[HD];      // W_p @ prev_gen0
__device__ float g_H2[S*HD];    // h2 state per step

__device__ __forceinline__ float sigm(float x) { return 1.f / (1.f + expf(-x)); }

// ---------------- zero the atomic accumulators ----------------
__global__ void k_zero() {
    int n = S*HD + HD*HD + 2*HD;
    for (int i = blockIdx.x*blockDim.x + threadIdx.x; i < n; i += gridDim.x*blockDim.x) {
        if (i < S*HD)               g_U[i] = 0.f;
        else if (i < S*HD + HD*HD)  g_M[i - S*HD] = 0.f;
        else if (i < S*HD + HD*HD + HD) g_v[i - S*HD - HD*HD] = 0.f;
        else                        g_w0[i - S*HD - HD*HD - HD] = 0.f;
    }
}

// ---------------- GEMM 1: U[128 x 64] = W_z[128,K] * Z^T[K,64] (split-K, NT) ----------------
__global__ void __launch_bounds__(256, 2) k_gemm_u(const float* __restrict__ fc1w,
                                                   const float* __restrict__ z) {
    __shared__ float As[128*33];
    __shared__ float Zs[64*33];
    int tid = threadIdx.x;
    int ty = tid >> 4, tx = tid & 15;
    float acc[8][4];
    #pragma unroll
    for (int r = 0; r < 8; r++)
        #pragma unroll
        for (int c = 0; c < 4; c++) acc[r][c] = 0.f;

    for (int st = blockIdx.x; st < NSUB; st += gridDim.x) {
        int kb = st << 5;
        for (int idx = tid; idx < 128*32; idx += 256) {
            int row = idx >> 5, kk = idx & 31;
            As[row*33 + kk] = fc1w[row*K2 + kb + kk];
        }
        for (int idx = tid; idx < 64*32; idx += 256) {
            int t = idx >> 5, kk = idx & 31;
            Zs[t*33 + kk] = z[t*NF + kb + kk];
        }
        __syncthreads();
        #pragma unroll
        for (int kk = 0; kk < 32; kk++) {
            float a[8], b[4];
            #pragma unroll
            for (int r = 0; r < 8; r++) a[r] = As[(ty + 16*r)*33 + kk];
            #pragma unroll
            for (int c = 0; c < 4; c++) b[c] = Zs[(tx + 16*c)*33 + kk];
            #pragma unroll
            for (int r = 0; r < 8; r++)
                #pragma unroll
                for (int c = 0; c < 4; c++) acc[r][c] += a[r]*b[c];
        }
        __syncthreads();
    }
    #pragma unroll
    for (int r = 0; r < 8; r++)
        #pragma unroll
        for (int c = 0; c < 4; c++)
            atomicAdd(&g_U[(tx + 16*c)*HD + (ty + 16*r)], acc[r][c]);
}

// ------- GEMM 2: M[128 x 128] = W_p[128,K] * fc2_w[K,128] (+ W_p@fc2_b, W_p@pg0) -------
__global__ void __launch_bounds__(256, 2) k_gemm_m(const float* __restrict__ fc1w,
                                                   const float* __restrict__ fc2w,
                                                   const float* __restrict__ fc2b,
                                                   const float* __restrict__ pg0) {
    __shared__ float As[128*33];
    __shared__ float Bs[32*128];
    __shared__ float Es[64];
    int tid = threadIdx.x;
    int ty = tid >> 4, tx = tid & 15;
    int erow = tid & 127, ewhich = tid >> 7;   // which: 0 -> fc2_b dot, 1 -> pg0 dot
    float acc[8][8];
    float accE = 0.f;
    #pragma unroll
    for (int r = 0; r < 8; r++)
        #pragma unroll
        for (int c = 0; c < 8; c++) acc[r][c] = 0.f;

    for (int st = blockIdx.x; st < NSUB; st += gridDim.x) {
        int kb = st << 5;
        for (int idx = tid; idx < 128*32; idx += 256) {
            int row = idx >> 5, kk = idx & 31;
            As[row*33 + kk] = fc1w[row*K2 + NF + kb + kk];
        }
        for (int idx = tid; idx < 32*128; idx += 256) {
            int kk = idx >> 7, c = idx & 127;
            Bs[kk*128 + c] = fc2w[(kb + kk)*128 + c];
        }
        if (tid < 64) Es[tid] = (tid < 32) ? fc2b[kb + tid] : pg0[kb + (tid - 32)];
        __syncthreads();
        #pragma unroll
        for (int kk = 0; kk < 32; kk++) {
            float a[8], b[8];
            #pragma unroll
            for (int r = 0; r < 8; r++) a[r] = As[(ty + 16*r)*33 + kk];
            #pragma unroll
            for (int c = 0; c < 8; c++) b[c] = Bs[kk*128 + tx + 16*c];
            #pragma unroll
            for (int r = 0; r < 8; r++)
                #pragma unroll
                for (int c = 0; c < 8; c++) acc[r][c] += a[r]*b[c];
            accE += As[erow*33 + kk] * Es[ewhich*32 + kk];
        }
        __syncthreads();
    }
    #pragma unroll
    for (int r = 0; r < 8; r++)
        #pragma unroll
        for (int c = 0; c < 8; c++)
            atomicAdd(&g_M[(ty + 16*r)*HD + (tx + 16*c)], acc[r][c]);   // row-major M
    atomicAdd(ewhich ? &g_w0[erow] : &g_v[erow], accE);
}

// ---------------- Phase 2: the 64-step recurrent scan ----------------
// v2: warp-per-row coalesced weight loads + shfl butterfly reduction.
// Each LDG.128 warp-instruction now covers one contiguous 512B row slice
// (4 wavefronts) instead of 32 scattered lines (32 wavefronts) -> 8x less
// L1tex pressure; per-step memory floor ~8.3K cyc instead of ~65K.
__global__ void __launch_bounds__(512) k_scan(
    const float* __restrict__ h1_in, const float* __restrict__ c1_in,
    const float* __restrict__ h2_in, const float* __restrict__ c2_in,
    const float* __restrict__ fc1b,
    const float* __restrict__ wih1, const float* __restrict__ whh1,
    const float* __restrict__ bih1, const float* __restrict__ bhh1,
    const float* __restrict__ wih2, const float* __restrict__ whh2,
    const float* __restrict__ bih2, const float* __restrict__ bhh2,
    float* __restrict__ out, int out_size)
{
    __shared__ __align__(16) float xs[HD], h1s[HD], c1s[HD], h2s[HD], c2s[HD];
    __shared__ float gs[4*HD];
    __shared__ float b1s[4*HD], b2s[4*HD], xbv[HD], xbw0[HD];
    int tid  = threadIdx.x;
    int warp = tid >> 5, lane = tid & 31;

    for (int i = tid; i < 4*HD; i += 512) { b1s[i] = bih1[i] + bhh1[i]; b2s[i] = bih2[i] + bhh2[i]; }
    if (tid < HD) {
        h1s[tid] = h1_in[tid]; c1s[tid] = c1_in[tid];
        h2s[tid] = h2_in[tid]; c2s[tid] = c2_in[tid];
        xbv[tid]  = fc1b[tid] + g_v[tid];
        xbw0[tid] = fc1b[tid] + g_w0[tid];
    }
    __syncthreads();

    for (int t = 0; t < S; t++) {
        // ---- x_t = relu(U_t + M@h2 + fc1_b + v)  (t=0: uses w0, no M term) ----
        if (t == 0) {
            if (tid < HD) xs[tid] = fmaxf(g_U[tid] + xbw0[tid], 0.f);
        } else {
            float4 hv = ((const float4*)h2s)[lane];
            #pragma unroll
            for (int i = 0; i < 8; i++) {
                int r = warp*8 + i;
                float4 m = ((const float4*)(g_M + r*HD))[lane];
                float p = m.x*hv.x + m.y*hv.y + m.z*hv.z + m.w*hv.w;
                #pragma unroll
                for (int off = 16; off; off >>= 1) p += __shfl_xor_sync(0xffffffffu, p, off);
                if (lane == 0) xs[r] = fmaxf(p + g_U[t*HD + r] + xbv[r], 0.f);
            }
        }
        __syncthreads();

        // ---- LSTM1 gates: 512 rows, 32 per warp, warp-per-row ----
        {
            float4 xv = ((const float4*)xs)[lane];
            float4 hv = ((const float4*)h1s)[lane];
            #pragma unroll 4
            for (int i = 0; i < 32; i++) {
                int r = warp*32 + i;
                float4 wi = ((const float4*)(wih1 + r*HD))[lane];
                float4 wh = ((const float4*)(whh1 + r*HD))[lane];
                float p = wi.x*xv.x + wi.y*xv.y + wi.z*xv.z + wi.w*xv.w
                        + wh.x*hv.x + wh.y*hv.y + wh.z*hv.z + wh.w*hv.w;
                #pragma unroll
                for (int off = 16; off; off >>= 1) p += __shfl_xor_sync(0xffffffffu, p, off);
                if (lane == 0) gs[r] = p + b1s[r];
            }
        }
        __syncthreads();
        if (tid < HD) {
            float gi = gs[tid], gf = gs[HD+tid], gg = gs[2*HD+tid], go = gs[3*HD+tid];
            float c = sigm(gf)*c1s[tid] + sigm(gi)*tanhf(gg);
            c1s[tid] = c;
            h1s[tid] = sigm(go)*tanhf(c);
        }
        __syncthreads();

        // ---- LSTM2 gates (input = h1) ----
        {
            float4 xv = ((const float4*)h1s)[lane];
            float4 hv = ((const float4*)h2s)[lane];
            #pragma unroll 4
            for (int i = 0; i < 32; i++) {
                int r = warp*32 + i;
                float4 wi = ((const float4*)(wih2 + r*HD))[lane];
                float4 wh = ((const float4*)(whh2 + r*HD))[lane];
                float p = wi.x*xv.x + wi.y*xv.y + wi.z*xv.z + wi.w*xv.w
                        + wh.x*hv.x + wh.y*hv.y + wh.z*hv.z + wh.w*hv.w;
                #pragma unroll
                for (int off = 16; off; off >>= 1) p += __shfl_xor_sync(0xffffffffu, p, off);
                if (lane == 0) gs[r] = p + b2s[r];
            }
        }
        __syncthreads();
        if (tid < HD) {
            float gi = gs[tid], gf = gs[HD+tid], gg = gs[2*HD+tid], go = gs[3*HD+tid];
            float c = sigm(gf)*c2s[tid] + sigm(gi)*tanhf(gg);
            c2s[tid] = c;
            float h = sigm(go)*tanhf(c);
            h2s[tid] = h;
            g_H2[t*HD + tid] = h;
        }
        __syncthreads();
    }

    if (out_size >= S*NF + 4*HD && tid < HD) {
        out[S*NF + 0*HD + tid] = h1s[tid];
        out[S*NF + 1*HD + tid] = c1s[tid];
        out[S*NF + 2*HD + tid] = h2s[tid];
        out[S*NF + 3*HD + tid] = c2s[tid];
    }
}

// ------- GEMM 3: out[t,k] = fc2_w[k,:] . h2_t + fc2_b[k] + y[t,k] (NT, K=128) -------
__global__ void __launch_bounds__(256) k_out(const float* __restrict__ fc2w,
                                             const float* __restrict__ fc2b,
                                             const float* __restrict__ y,
                                             float* __restrict__ out) {
    __shared__ __align__(16) float H2s[S*HD];
    int tid = threadIdx.x;
    for (int i = tid; i < S*HD; i += 256) H2s[i] = g_H2[i];
    __syncthreads();

    int k = blockIdx.x*256 + tid;
    const float4* w4 = (const float4*)(fc2w + k*HD);
    const float4* h4 = (const float4*)H2s;
    float acc[S];
    #pragma unroll
    for (int t = 0; t < S; t++) acc[t] = 0.f;

    #pragma unroll 4
    for (int j = 0; j < 32; j++) {
        float4 w = w4[j];
        #pragma unroll
        for (int t = 0; t < S; t++) {
            float4 h = h4[t*32 + j];
            acc[t] += w.x*h.x + w.y*h.y + w.z*h.z + w.w*h.w;
        }
    }
    float b = fc2b[k];
    #pragma unroll 4
    for (int t = 0; t < S; t++)
        out[t*NF + k] = acc[t] + b + y[t*NF + k];
}

// ---------------- launcher ----------------
extern "C" void kernel_launch(void* const* d_in, const int* in_sizes, int n_in,
                              void* d_out, int out_size) {
    const float* z    = (const float*)d_in[0];
    const float* y    = (const float*)d_in[1];
    const float* pg0  = (const float*)d_in[2];
    const float* h1   = (const float*)d_in[3];
    const float* c1   = (const float*)d_in[4];
    const float* h2   = (const float*)d_in[5];
    const float* c2   = (const float*)d_in[6];
    const float* fc1w = (const float*)d_in[7];
    const float* fc1b = (const float*)d_in[8];
    const float* wih1 = (const float*)d_in[9];
    const float* whh1 = (const float*)d_in[10];
    const float* bih1 = (const float*)d_in[11];
    const float* bhh1 = (const float*)d_in[12];
    const float* wih2 = (const float*)d_in[13];
    const float* whh2 = (const float*)d_in[14];
    const float* bih2 = (const float*)d_in[15];
    const float* bhh2 = (const float*)d_in[16];
    const float* fc2w = (const float*)d_in[17];
    const float* fc2b = (const float*)d_in[18];
    float* out = (float*)d_out;

    k_zero<<<32, 256>>>();
    k_gemm_u<<<296, 256>>>(fc1w, z);
    k_gemm_m<<<296, 256>>>(fc1w, fc2w, fc2b, pg0);
    k_scan<<<1, 512>>>(h1, c1, h2, c2, fc1b,
                       wih1, whh1, bih1, bhh1,
                       wih2, whh2, bih2, bhh2,
                       out, out_size);
    k_out<<<768, 256>>>(fc2w, fc2b, y, out);
}